// round 15
// baseline (speedup 1.0000x reference)
#include <cuda_runtime.h>
#include <cstdint>

#define T_TOKENS 16384
#define DIMX     2048
#define NE       8
#define KSEL     2048

// libdevice exp — exact bits, immune to fast-math flags.
extern "C" __device__ float __nv_expf(float);

// cp.async primitives (LDGSTS.128)
#define CP_ASYNC16(dst_u32, src_ptr) \
    asm volatile("cp.async.cg.shared.global [%0], [%1], 16;" :: "r"(dst_u32), "l"(src_ptr))
#define CP_COMMIT() asm volatile("cp.async.commit_group;" ::: "memory")
#define CP_WAIT2()  asm volatile("cp.async.wait_group 2;" ::: "memory")

// Scratch: per-expert sort keys (key = ~bits(sigmoid(logit))) and a global
// 14-bit histogram of keys per expert. g_hist is zero at module load and
// re-zeroed by k2 every call (replay-safe).
__device__ unsigned int g_keys[NE * T_TOKENS];
__device__ unsigned int g_hist[NE * 16384];

// ---------------------------------------------------------------------------
// Kernel 1: logits + keys + global key-histogram. (R14, unchanged: cp.async
// 4-stage ring, one barrier/chunk, bitwise-stable in-order fma.rn chains.)
// ---------------------------------------------------------------------------
#define K1T     128
#define TILE    64
#define CH      32
#define XP      36
#define STGF    (TILE * XP)
#define NSTG    4
#define WPP     4100

__global__ void __launch_bounds__(K1T) k1_gemv(const float* __restrict__ x,
                                               const float* __restrict__ W)
{
    extern __shared__ float sm[];
    float* swp = sm;                         // [4][WPP]  packed pairs, 65.6KB
    float* sx  = sm + 4 * WPP;               // [4][STGF] ring, 36.9KB

    const int tid  = threadIdx.x;
    const int lane = tid & 31;
    const int P    = tid >> 5;
    const int e0   = 2 * P, e1 = e0 + 1;
    const size_t rowBase = (size_t)blockIdx.x * TILE;

    {
        const float4* W0 = reinterpret_cast<const float4*>(W + e0 * DIMX);
        const float4* W1 = reinterpret_cast<const float4*>(W + e1 * DIMX);
        float* dst = swp + P * WPP;
#pragma unroll 4
        for (int it = 0; it < 16; ++it) {
            int d4 = it * 32 + lane;
            float4 w0 = W0[d4];
            float4 w1 = W1[d4];
            float4* dp = reinterpret_cast<float4*>(dst + d4 * 8);
            dp[0] = make_float4(w0.x, w1.x, w0.y, w1.y);
            dp[1] = make_float4(w0.z, w1.z, w0.w, w1.w);
        }
    }

    int rr[4], cc[4];
    unsigned sdst[4];
#pragma unroll
    for (int k = 0; k < 4; ++k) {
        int idx = tid + k * K1T;
        rr[k] = idx >> 3;
        cc[k] = idx & 7;
        sdst[k] = (unsigned)__cvta_generic_to_shared(&sx[rr[k] * XP + cc[k] * 4]);
    }

    const float* xb = x + rowBase * DIMX;

#pragma unroll
    for (int s = 0; s < NSTG - 1; ++s) {
#pragma unroll
        for (int k = 0; k < 4; ++k)
            CP_ASYNC16(sdst[k] + s * (STGF * 4),
                       xb + (size_t)rr[k] * DIMX + s * CH + cc[k] * 4);
        CP_COMMIT();
    }

    float a00 = 0.0f, a01 = 0.0f, a10 = 0.0f, a11 = 0.0f;
    const float* wb0 = swp + P * WPP;

    for (int ch = 0; ch < DIMX / CH; ++ch) {
        CP_WAIT2();
        __syncthreads();

        if (ch + NSTG - 1 < DIMX / CH) {
            const int s = (ch + NSTG - 1) & (NSTG - 1);
#pragma unroll
            for (int k = 0; k < 4; ++k)
                CP_ASYNC16(sdst[k] + s * (STGF * 4),
                           xb + (size_t)rr[k] * DIMX + (ch + NSTG - 1) * CH + cc[k] * 4);
        }
        CP_COMMIT();

        const float* x0p = sx + (ch & (NSTG - 1)) * STGF + lane * XP;
        const float* x1p = x0p + 32 * XP;
        const float* wb  = wb0 + ch * (CH * 2);
#pragma unroll
        for (int g = 0; g < 8; ++g) {
            float4 x0 = *reinterpret_cast<const float4*>(x0p + g * 4);
            float4 x1 = *reinterpret_cast<const float4*>(x1p + g * 4);
            float4 wA = *reinterpret_cast<const float4*>(wb + g * 8);
            float4 wB = *reinterpret_cast<const float4*>(wb + g * 8 + 4);
            a00 = __fmaf_rn(x0.x, wA.x, a00);  a01 = __fmaf_rn(x0.x, wA.y, a01);
            a10 = __fmaf_rn(x1.x, wA.x, a10);  a11 = __fmaf_rn(x1.x, wA.y, a11);
            a00 = __fmaf_rn(x0.y, wA.z, a00);  a01 = __fmaf_rn(x0.y, wA.w, a01);
            a10 = __fmaf_rn(x1.y, wA.z, a10);  a11 = __fmaf_rn(x1.y, wA.w, a11);
            a00 = __fmaf_rn(x0.z, wB.x, a00);  a01 = __fmaf_rn(x0.z, wB.y, a01);
            a10 = __fmaf_rn(x1.z, wB.x, a10);  a11 = __fmaf_rn(x1.z, wB.y, a11);
            a00 = __fmaf_rn(x0.w, wB.z, a00);  a01 = __fmaf_rn(x0.w, wB.w, a01);
            a10 = __fmaf_rn(x1.w, wB.z, a10);  a11 = __fmaf_rn(x1.w, wB.w, a11);
        }
    }

    const int t0 = (int)rowBase + lane;
    const int t1 = t0 + 32;
    float acc[4] = {a00, a01, a10, a11};
    const int eid[4] = {e0, e1, e0, e1};
    const int tok[4] = {t0, t0, t1, t1};
#pragma unroll
    for (int u = 0; u < 4; ++u) {
        float em = __nv_expf(-acc[u]);
        float s  = __fdiv_rn(1.0f, __fadd_rn(1.0f, em));
        unsigned key = ~__float_as_uint(s);
        g_keys[eid[u] * T_TOKENS + tok[u]] = key;
        unsigned h = (unsigned)eid[u] * 16384u + (key >> 18);
        unsigned m = __match_any_sync(0xffffffffu, h);
        if ((int)lane == __ffs(m) - 1)
            atomicAdd(&g_hist[h], (unsigned)__popc(m));
    }
}

// ---------------------------------------------------------------------------
// Kernel 2: per-expert exact top-2048 (desc, ties -> lower index).
// Level 0 scans g_hist into exclusive bin-starts start[16384]; Kstar via
// boundary-bin candidates (warp sort / candidate-local level / rare radix);
// then COUNTING-SORT SCATTER: selected key -> sel[atomicAdd(start[bin])],
// fixup = within-segment rank by comparison (segments avg ~1 elem).
// Replaces the 2048-element bitonic sort entirely.
// ---------------------------------------------------------------------------
#define K2_THREADS 1024
#define MASK46     ((1ull << 46) - 1)

__device__ __forceinline__ unsigned long long warp_sort64_pick(
    unsigned long long a, unsigned long long b, int idx, unsigned lane)
{
    const int g0 = (int)lane, g1 = (int)lane + 32;
    for (int k = 2; k <= 64; k <<= 1) {
        for (int j = k >> 1; j >= 1; j >>= 1) {
            if (j == 32) {
                bool asc = ((g0 & k) == 0);
                if ((a > b) == asc) { unsigned long long t = a; a = b; b = t; }
            } else {
                unsigned long long pa = __shfl_xor_sync(0xffffffffu, a, j);
                unsigned long long pb = __shfl_xor_sync(0xffffffffu, b, j);
                bool lower = ((lane & (unsigned)j) == 0u);
                bool ascA  = ((g0 & k) == 0);
                bool ascB  = ((g1 & k) == 0);
                unsigned long long amin = (a < pa) ? a : pa;
                unsigned long long amax = (a < pa) ? pa : a;
                unsigned long long bmin = (b < pb) ? b : pb;
                unsigned long long bmax = (b < pb) ? pb : b;
                a = (lower == ascA) ? amin : amax;
                b = (lower == ascB) ? bmin : bmax;
            }
        }
    }
    unsigned long long va = __shfl_sync(0xffffffffu, a, idx & 31);
    unsigned long long vb = __shfl_sync(0xffffffffu, b, idx & 31);
    return (idx < 32) ? va : vb;
}

__global__ void __launch_bounds__(K2_THREADS) k2_topk(float* __restrict__ out, int writeIdx)
{
    extern __shared__ unsigned char sm2[];
    unsigned int*        start = reinterpret_cast<unsigned int*>(sm2);              // 64KB
    unsigned int*        chist = reinterpret_cast<unsigned int*>(sm2 + 65536);      // 32KB
    unsigned int*        hscan = reinterpret_cast<unsigned int*>(sm2 + 98304);      // 16KB
    unsigned long long*  sel   = reinterpret_cast<unsigned long long*>(sm2 + 114688); // 16KB
    unsigned long long*  cand  = reinterpret_cast<unsigned long long*>(sm2 + 131072); // 16KB

    __shared__ unsigned int s_wsum[32];
    __shared__ unsigned long long s_pref;
    __shared__ unsigned long long s_mask;
    __shared__ unsigned long long s_kstar;
    __shared__ unsigned long long s_cand2[64];
    __shared__ int          s_want;
    __shared__ int          s_bin;
    __shared__ unsigned int s_before;
    __shared__ int          s_exact;
    __shared__ int          s_n;
    __shared__ int          s_bin2;
    __shared__ unsigned int s_before2;
    __shared__ int          s_exact2;
    __shared__ int          s_n2;

    const int e    = blockIdx.x;
    const int tid  = threadIdx.x;
    const unsigned lane = tid & 31;
    const int wid  = tid >> 5;

    unsigned kreg[16];
    {
        const unsigned* gk = g_keys + e * T_TOKENS;
#pragma unroll
        for (int r = 0; r < 16; ++r)
            kreg[r] = gk[tid + r * K2_THREADS];
    }

    if (tid == 0) { s_exact = 0; s_n = 0; s_exact2 = 0; s_n2 = 0; }
    __syncthreads();

    // ---- Level 0: scan g_hist -> exclusive bin starts + boundary bin ----
    {
        unsigned v[16];
        {
            const uint4* gh = reinterpret_cast<const uint4*>(g_hist + e * 16384);
#pragma unroll
            for (int q = 0; q < 4; ++q) {
                uint4 u = gh[tid * 4 + q];
                v[q * 4 + 0] = u.x; v[q * 4 + 1] = u.y;
                v[q * 4 + 2] = u.z; v[q * 4 + 3] = u.w;
            }
        }
        unsigned lsum = 0;
#pragma unroll
        for (int j = 0; j < 16; ++j) lsum += v[j];

        unsigned si = lsum;
#pragma unroll
        for (int o = 1; o < 32; o <<= 1) {
            unsigned n = __shfl_up_sync(0xffffffffu, si, o);
            if (lane >= (unsigned)o) si += n;
        }
        if (lane == 31) s_wsum[wid] = si;
        __syncthreads();
        if (wid == 0) {
            unsigned w = s_wsum[lane];
            unsigned wi = w;
#pragma unroll
            for (int o = 1; o < 32; o <<= 1) {
                unsigned n = __shfl_up_sync(0xffffffffu, wi, o);
                if (lane >= (unsigned)o) wi += n;
            }
            s_wsum[lane] = wi - w;
        }
        __syncthreads();
        unsigned base = s_wsum[wid] + (si - lsum);   // keys in bins < tid*16

        // write exclusive starts; find boundary bin
        unsigned run = base;
#pragma unroll
        for (int j = 0; j < 16; ++j) {
            start[tid * 16 + j] = run;
            unsigned c = v[j];
            if ((int)run < KSEL && (int)(run + c) >= KSEL) {
                s_bin = tid * 16 + j;
                s_before = run;
                if ((int)(run + c) == KSEL) s_exact = 1;
            }
            run += c;
        }
        __syncthreads();
        if (tid == 0) {
            s_want = KSEL - (int)s_before;
            s_pref = (unsigned long long)(unsigned)s_bin << 32;
            s_mask = 0x3FFFull << 32;
        }
        __syncthreads();
    }

    unsigned long long Kstar = 0ull;
    bool resolved = false;

    if (s_exact) {
        Kstar = s_pref | 0xFFFFFFFFull;
        resolved = true;
    } else {
        const unsigned binv = (unsigned)s_bin;
        const int want = s_want;

        // ---- Collect boundary-bin candidates (atomic-free two-pass) ----
        {
            int cw = 0;
#pragma unroll
            for (int r = 0; r < 16; ++r) {
                unsigned bal = __ballot_sync(0xffffffffu, (kreg[r] >> 18) == binv);
                cw += __popc(bal);
            }
            if (lane == 0) s_wsum[wid] = (unsigned)cw;
            __syncthreads();
            if (wid == 0) {
                unsigned w = s_wsum[lane];
                unsigned wi = w;
#pragma unroll
                for (int o = 1; o < 32; o <<= 1) {
                    unsigned n = __shfl_up_sync(0xffffffffu, wi, o);
                    if (lane >= (unsigned)o) wi += n;
                }
                s_wsum[lane] = wi - w;
                if (lane == 31) s_n = (int)wi;
            }
            __syncthreads();
            int base = (int)s_wsum[wid];
#pragma unroll
            for (int r = 0; r < 16; ++r) {
                bool c = ((kreg[r] >> 18) == binv);
                unsigned bal = __ballot_sync(0xffffffffu, c);
                if (c) {
                    int pos = base + __popc(bal & ((1u << lane) - 1u));
                    if (pos < 2048)
                        cand[pos] = ((unsigned long long)kreg[r] << 14)
                                  | (unsigned)(tid + r * K2_THREADS);
                }
                base += __popc(bal);
            }
        }
        __syncthreads();
        const int m = s_n;

        if (m <= 64) {
            if (wid == 0) {
                unsigned long long a = (lane < (unsigned)m) ? cand[lane] : ~0ull;
                unsigned long long b = (lane + 32 < (unsigned)m) ? cand[lane + 32] : ~0ull;
                unsigned long long ks = warp_sort64_pick(a, b, want - 1, lane);
                if (lane == 0) s_kstar = ks;
            }
            __syncthreads();
            Kstar = s_kstar;
            resolved = true;
        } else if (m <= 2048) {
            // ---- Candidate-local level: 4096 bins over K bits [20:32) ----
            for (int i = tid; i < 2 * 4096; i += K2_THREADS) chist[i] = 0u;
            __syncthreads();
#pragma unroll
            for (int q = 0; q < 2; ++q) {
                int j = tid + q * K2_THREADS;
                if (j < m) {
                    int bin = (int)((cand[j] >> 20) & 4095u);
                    atomicAdd(&chist[(wid & 1) * 4096 + bin], 1u);
                }
            }
            __syncthreads();
            {
                unsigned v[4];
                unsigned sthr = 0;
#pragma unroll
                for (int j = 0; j < 4; ++j) {
                    int b = 4 * tid + j;
                    v[j] = chist[b] + chist[4096 + b];
                    sthr += v[j];
                }
                unsigned si = sthr;
#pragma unroll
                for (int o = 1; o < 32; o <<= 1) {
                    unsigned n = __shfl_up_sync(0xffffffffu, si, o);
                    if (lane >= (unsigned)o) si += n;
                }
                if (lane == 31) s_wsum[wid] = si;
                __syncthreads();
                if (wid == 0) {
                    unsigned w = s_wsum[lane];
                    unsigned wi = w;
#pragma unroll
                    for (int o = 1; o < 32; o <<= 1) {
                        unsigned n = __shfl_up_sync(0xffffffffu, wi, o);
                        if (lane >= (unsigned)o) wi += n;
                    }
                    s_wsum[lane] = wi - w;
                }
                __syncthreads();
                unsigned run = s_wsum[wid] + (si - sthr);
#pragma unroll
                for (int j = 0; j < 4; ++j) {
                    unsigned p = run;
                    run += v[j];
                    if ((int)run >= want && (int)p < want) {
                        s_bin2 = 4 * tid + j;
                        s_before2 = p;
                        if ((int)run == want) s_exact2 = 1;
                    }
                }
            }
            __syncthreads();

            if (s_exact2) {
                Kstar = s_pref | ((unsigned long long)(unsigned)s_bin2 << 20)
                               | ((1ull << 20) - 1);
                resolved = true;
            } else {
                const unsigned b2 = (unsigned)s_bin2;
                const int want2 = want - (int)s_before2;
#pragma unroll
                for (int q = 0; q < 2; ++q) {
                    int j = tid + q * K2_THREADS;
                    if (j < m && (((cand[j] >> 20) & 4095u) == b2)) {
                        int pos = atomicAdd(&s_n2, 1);
                        if (pos < 64) s_cand2[pos] = cand[j];
                    }
                }
                __syncthreads();
                const int m2 = s_n2;
                if (m2 <= 64) {
                    if (wid == 0) {
                        unsigned long long a = (lane < (unsigned)m2) ? s_cand2[lane] : ~0ull;
                        unsigned long long b = (lane + 32 < (unsigned)m2) ? s_cand2[lane + 32] : ~0ull;
                        unsigned long long ks = warp_sort64_pick(a, b, want2 - 1, lane);
                        if (lane == 0) s_kstar = ks;
                    }
                    __syncthreads();
                    Kstar = s_kstar;
                    resolved = true;
                }
            }
        }

        if (!resolved) {
            // Rare path: radix over full keys within prefix (HC=2 copies in
            // chist; does NOT touch start[]).
            const int shifts[3] = {20, 10, 0};
            const int nbits [3] = {12, 10, 10};
            for (int lvl = 0; lvl < 3; ++lvl) {
                const int shift = shifts[lvl];
                const int nb    = 1 << nbits[lvl];
                const int wantLoc              = s_want;
                const unsigned long long mask  = s_mask;
                const unsigned long long pref  = s_pref;

                for (int i = tid; i < 2 * 4096; i += K2_THREADS) chist[i] = 0u;
                if (tid == 0) s_exact = 0;
                __syncthreads();

                unsigned int* myhist = chist + (wid & 1) * 4096;
#pragma unroll
                for (int r = 0; r < 16; ++r) {
                    unsigned long long K = ((unsigned long long)kreg[r] << 14)
                                         | (unsigned)(tid + r * K2_THREADS);
                    bool mm = ((K & mask) == pref);
                    unsigned active = __ballot_sync(0xffffffffu, mm);
                    if (mm) {
                        int bin = (int)((K >> shift) & (unsigned)(nb - 1));
                        unsigned same = __match_any_sync(active, bin);
                        if ((int)lane == (__ffs(same) - 1))
                            atomicAdd(&myhist[bin], (unsigned)__popc(same));
                    }
                }
                __syncthreads();
                {
                    unsigned v[4];
                    unsigned sthr = 0;
#pragma unroll
                    for (int j = 0; j < 4; ++j) {
                        int b = 4 * tid + j;
                        v[j] = (b < nb) ? (chist[b] + chist[4096 + b]) : 0u;
                        sthr += v[j];
                    }
                    unsigned si = sthr;
#pragma unroll
                    for (int o = 1; o < 32; o <<= 1) {
                        unsigned n = __shfl_up_sync(0xffffffffu, si, o);
                        if (lane >= (unsigned)o) si += n;
                    }
                    if (lane == 31) s_wsum[wid] = si;
                    __syncthreads();
                    if (wid == 0) {
                        unsigned w = s_wsum[lane];
                        unsigned wi = w;
#pragma unroll
                        for (int o = 1; o < 32; o <<= 1) {
                            unsigned n = __shfl_up_sync(0xffffffffu, wi, o);
                            if (lane >= (unsigned)o) wi += n;
                        }
                        s_wsum[lane] = wi - w;
                    }
                    __syncthreads();
                    unsigned run = s_wsum[wid] + (si - sthr);
#pragma unroll
                    for (int j = 0; j < 4; ++j) {
                        if (4 * tid + j < nb) {
                            run += v[j];
                            hscan[4 * tid + j] = run;
                        }
                    }
                }
                __syncthreads();
                for (int i = tid; i < nb; i += K2_THREADS) {
                    unsigned c = hscan[i];
                    unsigned p = (i > 0) ? hscan[i - 1] : 0u;
                    if ((int)c >= wantLoc && (int)p < wantLoc) {
                        s_bin = i; s_before = p;
                        if ((int)c == wantLoc) s_exact = 1;
                    }
                }
                __syncthreads();
                if (tid == 0) {
                    s_want = wantLoc - (int)s_before;
                    s_pref = pref | ((unsigned long long)(unsigned)s_bin << shift);
                    s_mask = mask | ((unsigned long long)(unsigned)(nb - 1) << shift);
                }
                __syncthreads();
                if (s_exact) break;
            }
            Kstar = s_pref | (~s_mask & MASK46);
        }
    }

    // ---- Counting-sort scatter: selected keys -> sel[], bumping start[] ----
#pragma unroll
    for (int r = 0; r < 16; ++r) {
        unsigned long long K = ((unsigned long long)kreg[r] << 14)
                             | (unsigned)(tid + r * K2_THREADS);
        if (K <= Kstar) {
            unsigned bin = kreg[r] >> 18;
            unsigned pos = atomicAdd(&start[bin], 1u);
            sel[pos] = K;
        }
    }
    __syncthreads();
    // Post-scatter invariant: for bins b <= s_bin, start[b] = segment end;
    // segment start = (b>0 ? start[b-1] : 0)  (bins < s_bin fully scattered).

    // ---- Fixup: final rank = segment start + within-segment rank ----
#pragma unroll
    for (int q = 0; q < 2; ++q) {
        int i = tid + q * K2_THREADS;
        unsigned long long K = sel[i];
        unsigned bin = (unsigned)(K >> 32);
        unsigned s = (bin > 0) ? start[bin - 1] : 0u;
        unsigned en = start[bin];
        unsigned rank = 0;
        for (unsigned j = s; j < en; ++j)
            rank += (sel[j] < K) ? 1u : 0u;
        unsigned p = s + rank;
        float score = __uint_as_float(~(unsigned)(K >> 14));
        out[e * KSEL + p] = score;
        if (writeIdx)
            out[NE * KSEL + e * KSEL + p] = (float)(unsigned)(K & 0x3FFFu);
    }

    // Re-zero this expert's g_hist slice (restores invariant for replay).
    {
        uint4 z = make_uint4(0u, 0u, 0u, 0u);
        uint4* gz = reinterpret_cast<uint4*>(g_hist + e * 16384);
        for (int i = tid; i < 16384 / 4; i += K2_THREADS) gz[i] = z;
    }
}

// ---------------------------------------------------------------------------
extern "C" void kernel_launch(void* const* d_in, const int* in_sizes, int n_in,
                              void* d_out, int out_size)
{
    const float* x = (const float*)d_in[0];   // [16384, 2048] f32
    const float* W = (const float*)d_in[1];   // [8, 2048] f32
    float* out = (float*)d_out;

    const int SMEM1 = (4 * WPP + NSTG * STGF) * (int)sizeof(float);   // 102464
    const int SMEM2 = 65536 + 32768 + 16384 + 16384 + 16384;          // 147456

    cudaFuncSetAttribute(k1_gemv, cudaFuncAttributeMaxDynamicSharedMemorySize, SMEM1);
    cudaFuncSetAttribute(k2_topk, cudaFuncAttributeMaxDynamicSharedMemorySize, SMEM2);

    const int writeIdx = (out_size >= 2 * NE * KSEL) ? 1 : 0;

    k1_gemv<<<T_TOKENS / TILE, K1T, SMEM1>>>(x, W);
    k2_topk<<<NE, K2_THREADS, SMEM2>>>(out, writeIdx);
}